// round 1
// baseline (speedup 1.0000x reference)
#include <cuda_runtime.h>
#include <math.h>

#define SS 512
#define BB 256
#define DD 256
#define NROWS (SS*BB)          // 131072
#define JROWS ((SS-2)*BB)      // 130560

// Scratch (static device allocations are the allowed scratch mechanism)
__device__ float g_h[(size_t)NROWS * DD];   // gelu(src @ map_w^T + map_b)
__device__ float g_t[(size_t)JROWS * DD];   // inner blacket result (reused 3x)

__device__ __forceinline__ float gelu_f(float x) {
    return 0.5f * x * (1.0f + erff(x * 0.7071067811865476f));
}

// Dual-A tiled GEMM with GELU epilogue.
//   out[n, j] (+)= gelu( sum_{k<256} A1[n+a1_off, k]   * W[j, k]
//                      + sum_{k<256} A2[n+a2_off, k]   * W[j, 256+k]   (KTOT==512 only)
//                      + bias[j] )
// MODE 0: OUT = gelu(...)                 (store)
// MODE 1: OUT = x + gelu(...), x = A1 shifted (a1_off), zero if row<0   (delta)
// MODE 2: OUT += gelu(...)                (J accumulate)
// A1 rows with (row + a1_off) < 0 read as zero (only happens in MODE 1 path).
template<int KTOT, int MODE>
__global__ void __launch_bounds__(256, 2) gemm_k(
    const float* __restrict__ A1, int a1_off,
    const float* __restrict__ A2, int a2_off,
    const float* __restrict__ W,
    const float* __restrict__ bias,
    float* __restrict__ OUT, int out_off)
{
    __shared__ float As[16][132];
    __shared__ float Ws[16][132];

    const int tid = threadIdx.x;
    const int tx = tid & 15;
    const int ty = tid >> 4;
    const int mbase = blockIdx.x * 128;
    const int nbase = blockIdx.y * 128;

    float acc[8][8];
    #pragma unroll
    for (int i = 0; i < 8; i++)
        #pragma unroll
        for (int j = 0; j < 8; j++) acc[i][j] = 0.f;

    for (int k0 = 0; k0 < KTOT; k0 += 16) {
        const float* Asrc;
        int aoff, kcol;
        if (KTOT == 512 && k0 >= 256) { Asrc = A2; aoff = a2_off; kcol = k0 - 256; }
        else                          { Asrc = A1; aoff = a1_off; kcol = k0;       }

        #pragma unroll
        for (int t = 0; t < 2; t++) {
            int v   = tid + t * 256;      // 0..511
            int rit = v >> 2;             // row in tile 0..127
            int c4  = (v & 3) << 2;       // k offset in tile {0,4,8,12}

            int grow = mbase + rit + aoff;
            float4 av = make_float4(0.f, 0.f, 0.f, 0.f);
            if (grow >= 0)
                av = *(const float4*)(Asrc + (size_t)grow * DD + kcol + c4);
            As[c4 + 0][rit] = av.x;
            As[c4 + 1][rit] = av.y;
            As[c4 + 2][rit] = av.z;
            As[c4 + 3][rit] = av.w;

            int wrow = nbase + rit;       // output col j
            float4 wv = *(const float4*)(W + (size_t)wrow * KTOT + k0 + c4);
            Ws[c4 + 0][rit] = wv.x;
            Ws[c4 + 1][rit] = wv.y;
            Ws[c4 + 2][rit] = wv.z;
            Ws[c4 + 3][rit] = wv.w;
        }
        __syncthreads();

        #pragma unroll
        for (int kk = 0; kk < 16; kk++) {
            float a[8], b[8];
            *(float4*)&a[0] = *(const float4*)&As[kk][ty * 8];
            *(float4*)&a[4] = *(const float4*)&As[kk][ty * 8 + 4];
            *(float4*)&b[0] = *(const float4*)&Ws[kk][tx * 8];
            *(float4*)&b[4] = *(const float4*)&Ws[kk][tx * 8 + 4];
            #pragma unroll
            for (int i = 0; i < 8; i++)
                #pragma unroll
                for (int j = 0; j < 8; j++)
                    acc[i][j] = fmaf(a[i], b[j], acc[i][j]);
        }
        __syncthreads();
    }

    // Epilogue
    float bj[8];
    #pragma unroll
    for (int j = 0; j < 8; j++) bj[j] = bias[nbase + tx * 8 + j];

    const int col = nbase + tx * 8;
    #pragma unroll
    for (int i = 0; i < 8; i++) {
        int row = mbase + ty * 8 + i;
        size_t obase = (size_t)(row + out_off) * DD + col;

        float xv[8];
        if (MODE == 1) {
            int xr = row + a1_off;
            if (xr >= 0) {
                *(float4*)&xv[0] = *(const float4*)(A1 + (size_t)xr * DD + col);
                *(float4*)&xv[4] = *(const float4*)(A1 + (size_t)xr * DD + col + 4);
            } else {
                #pragma unroll
                for (int j = 0; j < 8; j++) xv[j] = 0.f;
            }
        }

        #pragma unroll
        for (int j = 0; j < 8; j++) {
            float v = gelu_f(acc[i][j] + bj[j]);
            if (MODE == 0)      OUT[obase + j]  = v;
            else if (MODE == 1) OUT[obase + j]  = xv[j] + v;
            else                OUT[obase + j] += v;
        }
    }
}

// In-place cumsum over axis 0 (S steps of B*D columns), fully coalesced.
__global__ void cumsum_k(float* __restrict__ out) {
    int c = blockIdx.x * blockDim.x + threadIdx.x;  // 0 .. BB*DD-1
    float run = 0.f;
    #pragma unroll 4
    for (int s = 0; s < SS; s++) {
        size_t idx = (size_t)s * (BB * DD) + c;
        run += out[idx];
        out[idx] = run;
    }
}

extern "C" void kernel_launch(void* const* d_in, const int* in_sizes, int n_in,
                              void* d_out, int out_size)
{
    // Identify inputs by size where unique; biases in dict order.
    const float* src = nullptr;
    const float* map_w = nullptr;
    const float* bl_w = nullptr;
    const float* map_b = nullptr;
    const float* bl_b = nullptr;
    for (int i = 0; i < n_in; i++) {
        if (in_sizes[i] == NROWS * DD)      src  = (const float*)d_in[i];
        else if (in_sizes[i] == DD * DD)    map_w = (const float*)d_in[i];
        else if (in_sizes[i] == DD * 2*DD)  bl_w  = (const float*)d_in[i];
        else if (in_sizes[i] == DD) {
            if (!map_b) map_b = (const float*)d_in[i];
            else        bl_b  = (const float*)d_in[i];
        }
    }
    float* out = (float*)d_out;

    float* h; cudaGetSymbolAddress((void**)&h, g_h);
    float* t; cudaGetSymbolAddress((void**)&t, g_t);

    dim3 blk(256);
    dim3 gAll(NROWS / 128, 2);   // 1024 x 2
    dim3 gJ(JROWS / 128, 2);     // 1020 x 2

    // 1) h = gelu(src @ map_w^T + map_b)
    gemm_k<256, 0><<<gAll, blk>>>(src, 0, src, 0, map_w, map_b, h, 0);

    // 2) delta = x + blacket(x, h);  x = h shifted by one step (B rows), zero first
    gemm_k<512, 1><<<gAll, blk>>>(h, -BB, h, 0, bl_w, bl_b, out, 0);

    // 3) J terms, each: t = blacket(u, v); out[2B:] += gelu-blacket(w, t)
    // term 1: blacket(a, blacket(b, c))  : a=h[s], b=h[s+B], c=h[s+2B]
    gemm_k<512, 0><<<gJ, blk>>>(h, BB,    h, 2*BB, bl_w, bl_b, t, 0);
    gemm_k<512, 2><<<gJ, blk>>>(h, 0,     t, 0,    bl_w, bl_b, out, 2*BB);
    // term 2: blacket(b, blacket(c, a))
    gemm_k<512, 0><<<gJ, blk>>>(h, 2*BB,  h, 0,    bl_w, bl_b, t, 0);
    gemm_k<512, 2><<<gJ, blk>>>(h, BB,    t, 0,    bl_w, bl_b, out, 2*BB);
    // term 3: blacket(c, blacket(a, b))
    gemm_k<512, 0><<<gJ, blk>>>(h, 0,     h, BB,   bl_w, bl_b, t, 0);
    gemm_k<512, 2><<<gJ, blk>>>(h, 2*BB,  t, 0,    bl_w, bl_b, out, 2*BB);

    // 4) cumsum over axis 0, in place
    cumsum_k<<<(BB * DD) / 256, 256>>>(out);
}

// round 3
// speedup vs baseline: 2.4751x; 2.4751x over previous
#include <cuda_runtime.h>
#include <cuda_bf16.h>
#include <math.h>
#include <stdint.h>

#define SS 512
#define BB 256
#define DD 256
#define NROWS (SS*BB)          // 131072
#define JROWS ((SS-2)*BB)      // 130560

// ---------------- scratch ----------------
__device__ __align__(256) __nv_bfloat16 g_srch[(size_t)NROWS*DD];
__device__ __align__(256) __nv_bfloat16 g_srcl[(size_t)NROWS*DD];
__device__ __align__(256) __nv_bfloat16 g_hh[(size_t)NROWS*DD];
__device__ __align__(256) __nv_bfloat16 g_hl[(size_t)NROWS*DD];
__device__ __align__(256) __nv_bfloat16 g_th[(size_t)NROWS*DD];
__device__ __align__(256) __nv_bfloat16 g_tl[(size_t)NROWS*DD];
__device__ __align__(256) __nv_bfloat16 g_mwh[DD*DD];
__device__ __align__(256) __nv_bfloat16 g_mwl[DD*DD];
__device__ __align__(256) __nv_bfloat16 g_wh[DD*2*DD];
__device__ __align__(256) __nv_bfloat16 g_wl[DD*2*DD];

// ---------------- helpers (base PTX only: sm_80-level features) ----------------
__device__ __forceinline__ uint32_t smem_u32(const void* p) {
    uint32_t r;
    asm("{ .reg .u64 t; cvta.to.shared.u64 t, %1; cvt.u32.u64 %0, t; }" : "=r"(r) : "l"(p));
    return r;
}
__device__ __forceinline__ void cp16z(uint32_t dst, const void* src, uint32_t sz) {
    asm volatile("cp.async.cg.shared.global [%0], [%1], 16, %2;" :: "r"(dst), "l"(src), "r"(sz));
}
__device__ __forceinline__ void cp16(uint32_t dst, const void* src) {
    asm volatile("cp.async.cg.shared.global [%0], [%1], 16;" :: "r"(dst), "l"(src));
}
__device__ __forceinline__ void ldmx4(uint32_t* r, uint32_t addr) {
    asm volatile("ldmatrix.sync.aligned.m8n8.x4.shared.b16 {%0,%1,%2,%3}, [%4];"
                 : "=r"(r[0]), "=r"(r[1]), "=r"(r[2]), "=r"(r[3]) : "r"(addr));
}
__device__ __forceinline__ void mma16816(float* d, const uint32_t* a, uint32_t b0, uint32_t b1) {
    asm volatile("mma.sync.aligned.m16n8k16.row.col.f32.bf16.bf16.f32 "
                 "{%0,%1,%2,%3}, {%4,%5,%6,%7}, {%8,%9}, {%0,%1,%2,%3};"
                 : "+f"(d[0]), "+f"(d[1]), "+f"(d[2]), "+f"(d[3])
                 : "r"(a[0]), "r"(a[1]), "r"(a[2]), "r"(a[3]), "r"(b0), "r"(b1));
}
__device__ __forceinline__ float gelu_f(float x) {
    return 0.5f * x * (1.0f + erff(x * 0.7071067811865476f));
}
// swizzled offset within a 128x32-bf16 tile (64B rows, 4x16B chunks, xor by (r>>1)&3)
__device__ __forceinline__ uint32_t swz(int r, int c) {
    return (uint32_t)(r * 64 + ((c ^ ((r >> 1) & 3)) * 16));
}

// ---------------- split fp32 -> (hi, lo) bf16 ----------------
__global__ void split_k(const float* __restrict__ in, __nv_bfloat16* __restrict__ hi,
                        __nv_bfloat16* __restrict__ lo, int n) {
    int i = (blockIdx.x * blockDim.x + threadIdx.x) * 4;
    if (i >= n) return;
    float4 v = *(const float4*)(in + i);
    float a[4] = {v.x, v.y, v.z, v.w};
    __nv_bfloat16 h[4], l[4];
    #pragma unroll
    for (int j = 0; j < 4; j++) {
        h[j] = __float2bfloat16(a[j]);
        l[j] = __float2bfloat16(a[j] - __bfloat162float(h[j]));
    }
    __nv_bfloat162 t;
    t.x = h[0]; t.y = h[1]; *(__nv_bfloat162*)(hi + i)     = t;
    t.x = h[2]; t.y = h[3]; *(__nv_bfloat162*)(hi + i + 2) = t;
    t.x = l[0]; t.y = l[1]; *(__nv_bfloat162*)(lo + i)     = t;
    t.x = l[2]; t.y = l[3]; *(__nv_bfloat162*)(lo + i + 2) = t;
}

// ---------------- mma.sync GEMM ----------------
// CTA tile 128(M) x 128(N); 8 warps in 4(M) x 2(N); warp tile 32x64.
// Extended K = 3*KTOT via segments: seg0 (Ah,Wh), seg1 (Ah,Wl), seg2 (Al,Wh).
// MODE 0: outh/outl = bf16 hi/lo of gelu(.)
// MODE 1: outf = x + gelu(.) with x at row+a1_off (0 if row<0)
// MODE 2: outf[row+out_off] += gelu(.)
#define NSTG 3
#define STGB 16384            // A 8K + W 8K per stage
#define SMEM_BYTES (1024 + NSTG*STGB)

template<int KTOT, int MODE>
__global__ void __launch_bounds__(256, 2) mma_gemm(
    const __nv_bfloat16* __restrict__ a1h, const __nv_bfloat16* __restrict__ a1l, int a1_off,
    const __nv_bfloat16* __restrict__ a2h, const __nv_bfloat16* __restrict__ a2l, int a2_off,
    const __nv_bfloat16* __restrict__ wh,  const __nv_bfloat16* __restrict__ wl,
    const float* __restrict__ bias,
    float* __restrict__ outf, int out_off,
    __nv_bfloat16* __restrict__ outh, __nv_bfloat16* __restrict__ outl)
{
    constexpr int CPS = KTOT / 32;    // chunks per segment
    constexpr int NCH = 3 * CPS;      // total extended-K chunks
    extern __shared__ char smraw[];
    const uint32_t TIL = (smem_u32(smraw) + 1023u) & ~1023u;

    const int tid  = threadIdx.x;
    const int wid  = tid >> 5;
    const int lane = tid & 31;
    const int wm   = wid & 3;         // M warp index (0..3)
    const int wn   = wid >> 2;        // N warp index (0..1)
    const int mbase = blockIdx.x * 128;
    const int nbase = blockIdx.y * 128;

    float acc[2][8][4];
    #pragma unroll
    for (int i = 0; i < 2; i++)
        #pragma unroll
        for (int j = 0; j < 8; j++)
            #pragma unroll
            for (int k = 0; k < 4; k++) acc[i][j][k] = 0.f;

    auto load_chunk = [&](int c, int stg) {
        const int seg = c / CPS;
        const int k   = (c % CPS) * 32;
        const __nv_bfloat16 *Ah_, *Al_;
        int aoff, kk;
        if (KTOT == 512 && k >= 256) { Ah_ = a2h; Al_ = a2l; aoff = a2_off; kk = k - 256; }
        else                         { Ah_ = a1h; Al_ = a1l; aoff = a1_off; kk = k; }
        const __nv_bfloat16* A  = (seg == 2) ? Al_ : Ah_;
        const __nv_bfloat16* Wp = (seg == 1) ? wl  : wh;
        const uint32_t sb = TIL + (uint32_t)stg * STGB;
        #pragma unroll
        for (int v = tid; v < 1024; v += 256) {
            if (v < 512) {                       // A: 128 rows x 4 chunks of 16B
                int r = v >> 2, cc = v & 3;
                int grow = mbase + r + aoff;
                uint32_t sz = 16; int g = grow;
                if (g < 0) { g = 0; sz = 0; }
                cp16z(sb + swz(r, cc), A + (size_t)g * DD + kk + cc * 8, sz);
            } else {                             // W: 128 rows x 4 chunks of 16B
                int v2 = v - 512;
                int r = v2 >> 2, cc = v2 & 3;
                cp16(sb + 8192 + swz(r, cc), Wp + (size_t)(nbase + r) * KTOT + k + cc * 8);
            }
        }
        asm volatile("cp.async.commit_group;" ::: "memory");
    };

    load_chunk(0, 0);
    load_chunk(1, 1);

    for (int c = 0; c < NCH; ++c) {
        if (c == NCH - 1) asm volatile("cp.async.wait_group 0;" ::: "memory");
        else              asm volatile("cp.async.wait_group 1;" ::: "memory");
        __syncthreads();
        if (c + 2 < NCH) load_chunk(c + 2, (c + 2) % NSTG);

        const uint32_t sA = TIL + (uint32_t)(c % NSTG) * STGB;
        const uint32_t sW = sA + 8192;
        #pragma unroll
        for (int kh = 0; kh < 2; kh++) {
            const int c0 = kh * 2;                      // 16B chunk base within row
            uint32_t a[2][4];
            #pragma unroll
            for (int mf = 0; mf < 2; mf++) {
                int r  = wm * 32 + mf * 16 + (lane & 15);
                int cc = c0 + (lane >> 4);
                ldmx4(a[mf], sA + swz(r, cc));
            }
            uint32_t b[8][2];
            #pragma unroll
            for (int nb = 0; nb < 4; nb++) {
                int r  = wn * 64 + nb * 16 + (lane & 7) + ((lane >> 4) << 3);
                int cc = c0 + ((lane >> 3) & 1);
                uint32_t t4[4];
                ldmx4(t4, sW + swz(r, cc));
                b[2 * nb][0] = t4[0]; b[2 * nb][1] = t4[1];
                b[2 * nb + 1][0] = t4[2]; b[2 * nb + 1][1] = t4[3];
            }
            #pragma unroll
            for (int mf = 0; mf < 2; mf++)
                #pragma unroll
                for (int nf = 0; nf < 8; nf++)
                    mma16816(acc[mf][nf], a[mf], b[nf][0], b[nf][1]);
        }
    }

    // ---------------- epilogue ----------------
    // acc[mf][nf]: d0,d1 -> row (lane>>2), cols (lane&3)*2+{0,1}; d2,d3 -> row+8
    float2 bn[8];
    #pragma unroll
    for (int nf = 0; nf < 8; nf++) {
        int col = nbase + wn * 64 + nf * 8 + (lane & 3) * 2;
        bn[nf].x = bias[col];
        bn[nf].y = bias[col + 1];
    }

    #pragma unroll
    for (int mf = 0; mf < 2; mf++) {
        #pragma unroll
        for (int half = 0; half < 2; half++) {
            const int row = mbase + wm * 32 + mf * 16 + (lane >> 2) + half * 8;
            const int colb = nbase + wn * 64 + (lane & 3) * 2;
            #pragma unroll
            for (int nf = 0; nf < 8; nf++) {
                const int col = colb + nf * 8;
                float g0 = gelu_f(acc[mf][nf][half * 2 + 0] + bn[nf].x);
                float g1 = gelu_f(acc[mf][nf][half * 2 + 1] + bn[nf].y);
                if (MODE == 0) {
                    const size_t ob = (size_t)row * DD + col;
                    __nv_bfloat162 hv, lv;
                    hv.x = __float2bfloat16(g0);
                    hv.y = __float2bfloat16(g1);
                    lv.x = __float2bfloat16(g0 - __bfloat162float(hv.x));
                    lv.y = __float2bfloat16(g1 - __bfloat162float(hv.y));
                    *reinterpret_cast<__nv_bfloat162*>(outh + ob) = hv;
                    *reinterpret_cast<__nv_bfloat162*>(outl + ob) = lv;
                } else if (MODE == 1) {
                    const size_t ob = (size_t)row * DD + col;
                    const int xr = row + a1_off;
                    float2 o;
                    if (xr >= 0) {
                        const size_t xb = (size_t)xr * DD + col;
                        __nv_bfloat162 xh2 = *reinterpret_cast<const __nv_bfloat162*>(a1h + xb);
                        __nv_bfloat162 xl2 = *reinterpret_cast<const __nv_bfloat162*>(a1l + xb);
                        o.x = g0 + __bfloat162float(xh2.x) + __bfloat162float(xl2.x);
                        o.y = g1 + __bfloat162float(xh2.y) + __bfloat162float(xl2.y);
                    } else { o.x = g0; o.y = g1; }
                    *reinterpret_cast<float2*>(outf + ob) = o;
                } else {
                    const size_t ob = (size_t)(row + out_off) * DD + col;
                    float2 o = *reinterpret_cast<float2*>(outf + ob);
                    o.x += g0; o.y += g1;
                    *reinterpret_cast<float2*>(outf + ob) = o;
                }
            }
        }
    }
}

// ---------------- cumsum over axis 0, in place ----------------
__global__ void cumsum_k(float* __restrict__ out) {
    int c = blockIdx.x * blockDim.x + threadIdx.x;
    float run = 0.f;
    #pragma unroll 4
    for (int s = 0; s < SS; s++) {
        size_t idx = (size_t)s * (BB * DD) + c;
        run += out[idx];
        out[idx] = run;
    }
}

extern "C" void kernel_launch(void* const* d_in, const int* in_sizes, int n_in,
                              void* d_out, int out_size)
{
    const float* src = nullptr; const float* map_w = nullptr; const float* bl_w = nullptr;
    const float* map_b = nullptr; const float* bl_b = nullptr;
    for (int i = 0; i < n_in; i++) {
        if (in_sizes[i] == NROWS * DD)       src   = (const float*)d_in[i];
        else if (in_sizes[i] == DD * DD)     map_w = (const float*)d_in[i];
        else if (in_sizes[i] == DD * 2 * DD) bl_w  = (const float*)d_in[i];
        else if (in_sizes[i] == DD) { if (!map_b) map_b = (const float*)d_in[i]; else bl_b = (const float*)d_in[i]; }
    }
    float* out = (float*)d_out;

    __nv_bfloat16 *sh, *sl, *hh, *hl, *th, *tl, *mwh, *mwl, *wh, *wl;
    cudaGetSymbolAddress((void**)&sh,  g_srch); cudaGetSymbolAddress((void**)&sl,  g_srcl);
    cudaGetSymbolAddress((void**)&hh,  g_hh);   cudaGetSymbolAddress((void**)&hl,  g_hl);
    cudaGetSymbolAddress((void**)&th,  g_th);   cudaGetSymbolAddress((void**)&tl,  g_tl);
    cudaGetSymbolAddress((void**)&mwh, g_mwh);  cudaGetSymbolAddress((void**)&mwl, g_mwl);
    cudaGetSymbolAddress((void**)&wh,  g_wh);   cudaGetSymbolAddress((void**)&wl,  g_wl);

    cudaFuncSetAttribute(mma_gemm<256, 0>, cudaFuncAttributeMaxDynamicSharedMemorySize, SMEM_BYTES);
    cudaFuncSetAttribute(mma_gemm<512, 0>, cudaFuncAttributeMaxDynamicSharedMemorySize, SMEM_BYTES);
    cudaFuncSetAttribute(mma_gemm<512, 1>, cudaFuncAttributeMaxDynamicSharedMemorySize, SMEM_BYTES);
    cudaFuncSetAttribute(mma_gemm<512, 2>, cudaFuncAttributeMaxDynamicSharedMemorySize, SMEM_BYTES);

    split_k<<<(NROWS * DD / 4 + 255) / 256, 256>>>(src,   sh,  sl,  NROWS * DD);
    split_k<<<(DD * DD / 4 + 255) / 256, 256>>>(map_w, mwh, mwl, DD * DD);
    split_k<<<(DD * 2 * DD / 4 + 255) / 256, 256>>>(bl_w,  wh,  wl,  DD * 2 * DD);

    dim3 blk(256);
    dim3 gAll(NROWS / 128, 2);   // 1024 x 2
    dim3 gJ(JROWS / 128, 2);     // 1020 x 2

    // 1) h = gelu(src @ map_w^T + map_b) -> bf16 hi/lo
    mma_gemm<256, 0><<<gAll, blk, SMEM_BYTES>>>(sh, sl, 0, sh, sl, 0, mwh, mwl, map_b,
                                                nullptr, 0, hh, hl);
    // 2) delta = x + blacket(x, h), x = h shifted by one step (BB rows)
    mma_gemm<512, 1><<<gAll, blk, SMEM_BYTES>>>(hh, hl, -BB, hh, hl, 0, wh, wl, bl_b,
                                                out, 0, nullptr, nullptr);
    // 3) J terms: t = blacket(u, v); out[2B:] += blacket(w, t)
    mma_gemm<512, 0><<<gJ, blk, SMEM_BYTES>>>(hh, hl, BB,     hh, hl, 2 * BB, wh, wl, bl_b,
                                              nullptr, 0, th, tl);
    mma_gemm<512, 2><<<gJ, blk, SMEM_BYTES>>>(hh, hl, 0,      th, tl, 0,      wh, wl, bl_b,
                                              out, 2 * BB, nullptr, nullptr);
    mma_gemm<512, 0><<<gJ, blk, SMEM_BYTES>>>(hh, hl, 2 * BB, hh, hl, 0,      wh, wl, bl_b,
                                              nullptr, 0, th, tl);
    mma_gemm<512, 2><<<gJ, blk, SMEM_BYTES>>>(hh, hl, BB,     th, tl, 0,      wh, wl, bl_b,
                                              out, 2 * BB, nullptr, nullptr);
    mma_gemm<512, 0><<<gJ, blk, SMEM_BYTES>>>(hh, hl, 0,      hh, hl, BB,     wh, wl, bl_b,
                                              nullptr, 0, th, tl);
    mma_gemm<512, 2><<<gJ, blk, SMEM_BYTES>>>(hh, hl, 2 * BB, th, tl, 0,      wh, wl, bl_b,
                                              out, 2 * BB, nullptr, nullptr);
    // 4) cumsum along axis 0
    cumsum_k<<<(BB * DD) / 256, 256>>>(out);
}

// round 4
// speedup vs baseline: 3.8163x; 1.5419x over previous
#include <cuda_runtime.h>
#include <cuda_fp16.h>
#include <math.h>
#include <stdint.h>

#define SS 512
#define BB 256
#define DD 256
#define NROWS (SS*BB)          // 131072
#define JROWS ((SS-2)*BB)      // 130560

// ---------------- scratch ----------------
__device__ __align__(256) __half g_srch[(size_t)NROWS*DD];
__device__ __align__(256) __half g_srcl[(size_t)NROWS*DD];
__device__ __align__(256) __half g_hh[(size_t)NROWS*DD];
__device__ __align__(256) __half g_hl[(size_t)NROWS*DD];
__device__ __align__(256) __half g_th[(size_t)NROWS*DD];
__device__ __align__(256) __half g_tl[(size_t)NROWS*DD];
__device__ __align__(256) __half g_mw[DD*DD];
__device__ __align__(256) __half g_w[DD*2*DD];

// ---------------- helpers (base PTX, sm_80-level) ----------------
__device__ __forceinline__ uint32_t smem_u32(const void* p) {
    uint32_t r;
    asm("{ .reg .u64 t; cvta.to.shared.u64 t, %1; cvt.u32.u64 %0, t; }" : "=r"(r) : "l"(p));
    return r;
}
__device__ __forceinline__ void cp16z(uint32_t dst, const void* src, uint32_t sz) {
    asm volatile("cp.async.cg.shared.global [%0], [%1], 16, %2;" :: "r"(dst), "l"(src), "r"(sz));
}
__device__ __forceinline__ void cp16(uint32_t dst, const void* src) {
    asm volatile("cp.async.cg.shared.global [%0], [%1], 16;" :: "r"(dst), "l"(src));
}
__device__ __forceinline__ void ldmx4(uint32_t* r, uint32_t addr) {
    asm volatile("ldmatrix.sync.aligned.m8n8.x4.shared.b16 {%0,%1,%2,%3}, [%4];"
                 : "=r"(r[0]), "=r"(r[1]), "=r"(r[2]), "=r"(r[3]) : "r"(addr));
}
__device__ __forceinline__ void mma16816(float* d, const uint32_t* a, uint32_t b0, uint32_t b1) {
    asm volatile("mma.sync.aligned.m16n8k16.row.col.f32.f16.f16.f32 "
                 "{%0,%1,%2,%3}, {%4,%5,%6,%7}, {%8,%9}, {%0,%1,%2,%3};"
                 : "+f"(d[0]), "+f"(d[1]), "+f"(d[2]), "+f"(d[3])
                 : "r"(a[0]), "r"(a[1]), "r"(a[2]), "r"(a[3]), "r"(b0), "r"(b1));
}
__device__ __forceinline__ float gelu_f(float x) {
    return 0.5f * x * (1.0f + erff(x * 0.7071067811865476f));
}
// swizzled offset within a 128x32-fp16 tile (64B rows, 4x16B chunks)
__device__ __forceinline__ uint32_t swz(int r, int c) {
    return (uint32_t)(r * 64 + ((c ^ ((r >> 1) & 3)) * 16));
}

// ---------------- split fp32 -> (hi, lo) fp16 ----------------
__global__ void split_k(const float* __restrict__ in, __half* __restrict__ hi,
                        __half* __restrict__ lo, int n) {
    int i = (blockIdx.x * blockDim.x + threadIdx.x) * 4;
    if (i >= n) return;
    float4 v = *(const float4*)(in + i);
    float a[4] = {v.x, v.y, v.z, v.w};
    __half h[4], l[4];
    #pragma unroll
    for (int j = 0; j < 4; j++) {
        h[j] = __float2half(a[j]);
        l[j] = __float2half(a[j] - __half2float(h[j]));
    }
    __half2 t;
    t.x = h[0]; t.y = h[1]; *(__half2*)(hi + i)     = t;
    t.x = h[2]; t.y = h[3]; *(__half2*)(hi + i + 2) = t;
    t.x = l[0]; t.y = l[1]; *(__half2*)(lo + i)     = t;
    t.x = l[2]; t.y = l[3]; *(__half2*)(lo + i + 2) = t;
}
// fp32 -> single fp16
__global__ void conv_k(const float* __restrict__ in, __half* __restrict__ o, int n) {
    int i = (blockIdx.x * blockDim.x + threadIdx.x) * 4;
    if (i >= n) return;
    float4 v = *(const float4*)(in + i);
    __half2 t;
    t.x = __float2half(v.x); t.y = __float2half(v.y); *(__half2*)(o + i)     = t;
    t.x = __float2half(v.z); t.y = __float2half(v.w); *(__half2*)(o + i + 2) = t;
}

// ---------------- mma.sync GEMM, 2-term fp16 split ----------------
// CTA tile 128(M) x 128(N); 8 warps 4(M) x 2(N); warp tile 32x64.
// out = gelu( (A1h+A1l)[n+a1_off] @ W[:, :256]^T (+ (A2h+A2l) @ W[:, 256:]^T) + bias )
// MODE 0: outh/outl = fp16 hi/lo of gelu(.)
// MODE 1: outf = x + gelu(.), x = (a1h+a1l)[row+a1_off] (0 if row<0)
// MODE 2: outf[row+out_off] += gelu(.)
#define NSTG 3
#define STGB 24576            // Ah 8K + Al 8K + W 8K per stage
#define SMEM_BYTES (1024 + NSTG*STGB)

template<int KTOT, int MODE>
__global__ void __launch_bounds__(256, 2) mma_gemm(
    const __half* __restrict__ a1h, const __half* __restrict__ a1l, int a1_off,
    const __half* __restrict__ a2h, const __half* __restrict__ a2l, int a2_off,
    const __half* __restrict__ w,
    const float* __restrict__ bias,
    float* __restrict__ outf, int out_off,
    __half* __restrict__ outh, __half* __restrict__ outl)
{
    constexpr int NCH = KTOT / 32;
    extern __shared__ char smraw[];
    const uint32_t TIL = (smem_u32(smraw) + 1023u) & ~1023u;

    const int tid  = threadIdx.x;
    const int wid  = tid >> 5;
    const int lane = tid & 31;
    const int wm   = wid & 3;
    const int wn   = wid >> 2;
    const int mbase = blockIdx.x * 128;
    const int nbase = blockIdx.y * 128;

    float acc[2][8][4];
    #pragma unroll
    for (int i = 0; i < 2; i++)
        #pragma unroll
        for (int j = 0; j < 8; j++)
            #pragma unroll
            for (int k = 0; k < 4; k++) acc[i][j][k] = 0.f;

    auto load_chunk = [&](int c, int stg) {
        const int k = c * 32;
        const __half *Ah_, *Al_;
        int aoff, kk;
        if (KTOT == 512 && k >= 256) { Ah_ = a2h; Al_ = a2l; aoff = a2_off; kk = k - 256; }
        else                         { Ah_ = a1h; Al_ = a1l; aoff = a1_off; kk = k; }
        const uint32_t sb = TIL + (uint32_t)stg * STGB;
        #pragma unroll
        for (int v = tid; v < 1536; v += 256) {
            if (v < 1024) {                      // Ah / Al: 2 x 128 rows x 4 x 16B
                int split = v >> 9, r = (v >> 2) & 127, cc = v & 3;
                int grow = mbase + r + aoff;
                uint32_t sz = 16; int g = grow;
                if (g < 0) { g = 0; sz = 0; }
                const __half* src = split ? Al_ : Ah_;
                cp16z(sb + (uint32_t)split * 8192u + swz(r, cc),
                      src + (size_t)g * DD + kk + cc * 8, sz);
            } else {                             // W: 128 rows x 4 x 16B
                int v2 = v - 1024;
                int r = v2 >> 2, cc = v2 & 3;
                cp16(sb + 16384u + swz(r, cc), w + (size_t)(nbase + r) * KTOT + k + cc * 8);
            }
        }
        asm volatile("cp.async.commit_group;" ::: "memory");
    };

    load_chunk(0, 0);
    load_chunk(1, 1);

    for (int c = 0; c < NCH; ++c) {
        if (c == NCH - 1) asm volatile("cp.async.wait_group 0;" ::: "memory");
        else              asm volatile("cp.async.wait_group 1;" ::: "memory");
        __syncthreads();
        if (c + 2 < NCH) load_chunk(c + 2, (c + 2) % NSTG);

        const uint32_t sA = TIL + (uint32_t)(c % NSTG) * STGB;
        const uint32_t sW = sA + 16384;
        #pragma unroll
        for (int kh = 0; kh < 2; kh++) {
            const int c0 = kh * 2;
            uint32_t ah[2][4], al[2][4];
            #pragma unroll
            for (int mf = 0; mf < 2; mf++) {
                int r  = wm * 32 + mf * 16 + (lane & 15);
                int cc = c0 + (lane >> 4);
                ldmx4(ah[mf], sA + swz(r, cc));
                ldmx4(al[mf], sA + 8192u + swz(r, cc));
            }
            uint32_t b[8][2];
            #pragma unroll
            for (int nb = 0; nb < 4; nb++) {
                int r  = wn * 64 + nb * 16 + (lane & 7) + ((lane >> 4) << 3);
                int cc = c0 + ((lane >> 3) & 1);
                uint32_t t4[4];
                ldmx4(t4, sW + swz(r, cc));
                b[2 * nb][0] = t4[0];     b[2 * nb][1] = t4[1];
                b[2 * nb + 1][0] = t4[2]; b[2 * nb + 1][1] = t4[3];
            }
            #pragma unroll
            for (int mf = 0; mf < 2; mf++)
                #pragma unroll
                for (int nf = 0; nf < 8; nf++) {
                    mma16816(acc[mf][nf], ah[mf], b[nf][0], b[nf][1]);
                    mma16816(acc[mf][nf], al[mf], b[nf][0], b[nf][1]);
                }
        }
    }

    // ---------------- epilogue ----------------
    float2 bn[8];
    #pragma unroll
    for (int nf = 0; nf < 8; nf++) {
        int col = nbase + wn * 64 + nf * 8 + (lane & 3) * 2;
        bn[nf].x = bias[col];
        bn[nf].y = bias[col + 1];
    }

    #pragma unroll
    for (int mf = 0; mf < 2; mf++) {
        #pragma unroll
        for (int half = 0; half < 2; half++) {
            const int row = mbase + wm * 32 + mf * 16 + (lane >> 2) + half * 8;
            const int colb = nbase + wn * 64 + (lane & 3) * 2;
            #pragma unroll
            for (int nf = 0; nf < 8; nf++) {
                const int col = colb + nf * 8;
                float g0 = gelu_f(acc[mf][nf][half * 2 + 0] + bn[nf].x);
                float g1 = gelu_f(acc[mf][nf][half * 2 + 1] + bn[nf].y);
                if (MODE == 0) {
                    const size_t ob = (size_t)row * DD + col;
                    __half2 hv, lv;
                    hv.x = __float2half(g0);
                    hv.y = __float2half(g1);
                    lv.x = __float2half(g0 - __half2float(hv.x));
                    lv.y = __float2half(g1 - __half2float(hv.y));
                    *reinterpret_cast<__half2*>(outh + ob) = hv;
                    *reinterpret_cast<__half2*>(outl + ob) = lv;
                } else if (MODE == 1) {
                    const size_t ob = (size_t)row * DD + col;
                    const int xr = row + a1_off;
                    float2 o;
                    if (xr >= 0) {
                        const size_t xb = (size_t)xr * DD + col;
                        __half2 xh2 = *reinterpret_cast<const __half2*>(a1h + xb);
                        __half2 xl2 = *reinterpret_cast<const __half2*>(a1l + xb);
                        o.x = g0 + __half2float(xh2.x) + __half2float(xl2.x);
                        o.y = g1 + __half2float(xh2.y) + __half2float(xl2.y);
                    } else { o.x = g0; o.y = g1; }
                    *reinterpret_cast<float2*>(outf + ob) = o;
                } else {
                    const size_t ob = (size_t)(row + out_off) * DD + col;
                    float2 o = *reinterpret_cast<float2*>(outf + ob);
                    o.x += g0; o.y += g1;
                    *reinterpret_cast<float2*>(outf + ob) = o;
                }
            }
        }
    }
}

// ---------------- cumsum over axis 0, in place ----------------
__global__ void cumsum_k(float* __restrict__ out) {
    int c = blockIdx.x * blockDim.x + threadIdx.x;
    float run = 0.f;
    #pragma unroll 4
    for (int s = 0; s < SS; s++) {
        size_t idx = (size_t)s * (BB * DD) + c;
        run += out[idx];
        out[idx] = run;
    }
}

extern "C" void kernel_launch(void* const* d_in, const int* in_sizes, int n_in,
                              void* d_out, int out_size)
{
    const float* src = nullptr; const float* map_w = nullptr; const float* bl_w = nullptr;
    const float* map_b = nullptr; const float* bl_b = nullptr;
    for (int i = 0; i < n_in; i++) {
        if (in_sizes[i] == NROWS * DD)       src   = (const float*)d_in[i];
        else if (in_sizes[i] == DD * DD)     map_w = (const float*)d_in[i];
        else if (in_sizes[i] == DD * 2 * DD) bl_w  = (const float*)d_in[i];
        else if (in_sizes[i] == DD) { if (!map_b) map_b = (const float*)d_in[i]; else bl_b = (const float*)d_in[i]; }
    }
    float* out = (float*)d_out;

    __half *sh, *sl, *hh, *hl, *th, *tl, *mw, *w;
    cudaGetSymbolAddress((void**)&sh, g_srch); cudaGetSymbolAddress((void**)&sl, g_srcl);
    cudaGetSymbolAddress((void**)&hh, g_hh);   cudaGetSymbolAddress((void**)&hl, g_hl);
    cudaGetSymbolAddress((void**)&th, g_th);   cudaGetSymbolAddress((void**)&tl, g_tl);
    cudaGetSymbolAddress((void**)&mw, g_mw);   cudaGetSymbolAddress((void**)&w,  g_w);

    cudaFuncSetAttribute(mma_gemm<256, 0>, cudaFuncAttributeMaxDynamicSharedMemorySize, SMEM_BYTES);
    cudaFuncSetAttribute(mma_gemm<512, 0>, cudaFuncAttributeMaxDynamicSharedMemorySize, SMEM_BYTES);
    cudaFuncSetAttribute(mma_gemm<512, 1>, cudaFuncAttributeMaxDynamicSharedMemorySize, SMEM_BYTES);
    cudaFuncSetAttribute(mma_gemm<512, 2>, cudaFuncAttributeMaxDynamicSharedMemorySize, SMEM_BYTES);

    split_k<<<(NROWS * DD / 4 + 255) / 256, 256>>>(src, sh, sl, NROWS * DD);
    conv_k<<<(DD * DD / 4 + 255) / 256, 256>>>(map_w, mw, DD * DD);
    conv_k<<<(DD * 2 * DD / 4 + 255) / 256, 256>>>(bl_w, w, DD * 2 * DD);

    dim3 blk(256);
    dim3 gAll(NROWS / 128, 2);   // 1024 x 2
    dim3 gJ(JROWS / 128, 2);     // 1020 x 2

    // 1) h = gelu(src @ map_w^T + map_b) -> fp16 hi/lo
    mma_gemm<256, 0><<<gAll, blk, SMEM_BYTES>>>(sh, sl, 0, sh, sl, 0, mw, map_b,
                                                nullptr, 0, hh, hl);
    // 2) delta = x + blacket(x, h), x = h shifted by one step (BB rows)
    mma_gemm<512, 1><<<gAll, blk, SMEM_BYTES>>>(hh, hl, -BB, hh, hl, 0, w, bl_b,
                                                out, 0, nullptr, nullptr);
    // 3) J terms: t = blacket(u, v); out[2B:] += blacket(w, t)
    mma_gemm<512, 0><<<gJ, blk, SMEM_BYTES>>>(hh, hl, BB,     hh, hl, 2 * BB, w, bl_b,
                                              nullptr, 0, th, tl);
    mma_gemm<512, 2><<<gJ, blk, SMEM_BYTES>>>(hh, hl, 0,      th, tl, 0,      w, bl_b,
                                              out, 2 * BB, nullptr, nullptr);
    mma_gemm<512, 0><<<gJ, blk, SMEM_BYTES>>>(hh, hl, 2 * BB, hh, hl, 0,      w, bl_b,
                                              nullptr, 0, th, tl);
    mma_gemm<512, 2><<<gJ, blk, SMEM_BYTES>>>(hh, hl, BB,     th, tl, 0,      w, bl_b,
                                              out, 2 * BB, nullptr, nullptr);
    mma_gemm<512, 0><<<gJ, blk, SMEM_BYTES>>>(hh, hl, 0,      hh, hl, BB,     w, bl_b,
                                              nullptr, 0, th, tl);
    mma_gemm<512, 2><<<gJ, blk, SMEM_BYTES>>>(hh, hl, 2 * BB, th, tl, 0,      w, bl_b,
                                              out, 2 * BB, nullptr, nullptr);
    // 4) cumsum along axis 0
    cumsum_k<<<(BB * DD) / 256, 256>>>(out);
}

// round 5
// speedup vs baseline: 6.1784x; 1.6189x over previous
#include <cuda_runtime.h>
#include <cuda_fp16.h>
#include <math.h>
#include <stdint.h>

#define SS 512
#define BB 256
#define DD 256
#define NROWS (SS*BB)          // 131072
#define JROWS ((SS-2)*BB)      // 130560

// ---------------- scratch ----------------
__device__ __align__(256) __half g_src[(size_t)NROWS*DD];
__device__ __align__(256) __half g_h[(size_t)NROWS*DD];
__device__ __align__(256) __half g_t[(size_t)NROWS*DD];
__device__ __align__(256) __half g_mw[DD*DD];
__device__ __align__(256) __half g_w[DD*2*DD];

// ---------------- helpers (base PTX, sm_80-level) ----------------
__device__ __forceinline__ uint32_t smem_u32(const void* p) {
    uint32_t r;
    asm("{ .reg .u64 t; cvta.to.shared.u64 t, %1; cvt.u32.u64 %0, t; }" : "=r"(r) : "l"(p));
    return r;
}
__device__ __forceinline__ void cp16z(uint32_t dst, const void* src, uint32_t sz) {
    asm volatile("cp.async.cg.shared.global [%0], [%1], 16, %2;" :: "r"(dst), "l"(src), "r"(sz));
}
__device__ __forceinline__ void cp16(uint32_t dst, const void* src) {
    asm volatile("cp.async.cg.shared.global [%0], [%1], 16;" :: "r"(dst), "l"(src));
}
__device__ __forceinline__ void ldmx4(uint32_t* r, uint32_t addr) {
    asm volatile("ldmatrix.sync.aligned.m8n8.x4.shared.b16 {%0,%1,%2,%3}, [%4];"
                 : "=r"(r[0]), "=r"(r[1]), "=r"(r[2]), "=r"(r[3]) : "r"(addr));
}
__device__ __forceinline__ void mma16816(float* d, const uint32_t* a, uint32_t b0, uint32_t b1) {
    asm volatile("mma.sync.aligned.m16n8k16.row.col.f32.f16.f16.f32 "
                 "{%0,%1,%2,%3}, {%4,%5,%6,%7}, {%8,%9}, {%0,%1,%2,%3};"
                 : "+f"(d[0]), "+f"(d[1]), "+f"(d[2]), "+f"(d[3])
                 : "r"(a[0]), "r"(a[1]), "r"(a[2]), "r"(a[3]), "r"(b0), "r"(b1));
}
__device__ __forceinline__ float gelu_f(float x) {
    return 0.5f * x * (1.0f + erff(x * 0.7071067811865476f));
}
// swizzled offset within a 128-row x 64-col fp16 tile (128B rows, 8 x 16B chunks)
__device__ __forceinline__ uint32_t swz(int r, int c) {
    return (uint32_t)(r * 128 + ((c ^ (r & 7)) * 16));
}

// ---------------- fp32 -> fp16 ----------------
__global__ void conv_k(const float* __restrict__ in, __half* __restrict__ o, int n) {
    int i = (blockIdx.x * blockDim.x + threadIdx.x) * 4;
    if (i >= n) return;
    float4 v = *(const float4*)(in + i);
    __half2 t;
    t.x = __float2half(v.x); t.y = __float2half(v.y); *(__half2*)(o + i)     = t;
    t.x = __float2half(v.z); t.y = __float2half(v.w); *(__half2*)(o + i + 2) = t;
}

// ---------------- mma.sync GEMM, single fp16 ----------------
// CTA tile 128(M) x 128(N); 8 warps 4(M) x 2(N); warp tile 32x64; K-chunk 64.
// out = gelu( A1[n+a1_off] @ W[:, :256]^T (+ A2 @ W[:, 256:]^T) + bias )
// MODE 0: outh = fp16(gelu(.))
// MODE 1: outf = x + gelu(.), x = a1[row+a1_off] (0 if row<0)
// MODE 2: outf[row+out_off] += gelu(.)
#define NSTG 3
#define STGB 32768            // A 16K + W 16K per stage
#define SMEM_BYTES (1024 + NSTG*STGB)

template<int KTOT, int MODE>
__global__ void __launch_bounds__(256, 2) mma_gemm(
    const __half* __restrict__ a1, int a1_off,
    const __half* __restrict__ a2, int a2_off,
    const __half* __restrict__ w,
    const float* __restrict__ bias,
    float* __restrict__ outf, int out_off,
    __half* __restrict__ outh)
{
    constexpr int NCH = KTOT / 64;
    extern __shared__ char smraw[];
    const uint32_t TIL = (smem_u32(smraw) + 1023u) & ~1023u;

    const int tid  = threadIdx.x;
    const int wid  = tid >> 5;
    const int lane = tid & 31;
    const int wm   = wid & 3;
    const int wn   = wid >> 2;
    const int mbase = blockIdx.x * 128;
    const int nbase = blockIdx.y * 128;

    float acc[2][8][4];
    #pragma unroll
    for (int i = 0; i < 2; i++)
        #pragma unroll
        for (int j = 0; j < 8; j++)
            #pragma unroll
            for (int k = 0; k < 4; k++) acc[i][j][k] = 0.f;

    auto load_chunk = [&](int c, int stg) {
        const int k = c * 64;
        const __half* A_;
        int aoff, kk;
        if (KTOT == 512 && k >= 256) { A_ = a2; aoff = a2_off; kk = k - 256; }
        else                         { A_ = a1; aoff = a1_off; kk = k; }
        const uint32_t sb = TIL + (uint32_t)stg * STGB;
        #pragma unroll
        for (int v = tid; v < 2048; v += 256) {
            if (v < 1024) {                      // A: 128 rows x 8 x 16B
                int r = v >> 3, cc = v & 7;
                int grow = mbase + r + aoff;
                uint32_t sz = 16; int g = grow;
                if (g < 0) { g = 0; sz = 0; }
                cp16z(sb + swz(r, cc), A_ + (size_t)g * DD + kk + cc * 8, sz);
            } else {                             // W: 128 rows x 8 x 16B
                int v2 = v - 1024;
                int r = v2 >> 3, cc = v2 & 7;
                cp16(sb + 16384u + swz(r, cc), w + (size_t)(nbase + r) * KTOT + k + cc * 8);
            }
        }
        asm volatile("cp.async.commit_group;" ::: "memory");
    };

    load_chunk(0, 0);
    if (NCH > 1) load_chunk(1, 1);

    for (int c = 0; c < NCH; ++c) {
        if (c == NCH - 1) asm volatile("cp.async.wait_group 0;" ::: "memory");
        else              asm volatile("cp.async.wait_group 1;" ::: "memory");
        __syncthreads();
        if (c + 2 < NCH) load_chunk(c + 2, (c + 2) % NSTG);

        const uint32_t sA = TIL + (uint32_t)(c % NSTG) * STGB;
        const uint32_t sW = sA + 16384;
        #pragma unroll
        for (int kh = 0; kh < 4; kh++) {
            const int c0 = kh * 2;               // 16B-chunk base within 128B row
            uint32_t a[2][4];
            #pragma unroll
            for (int mf = 0; mf < 2; mf++) {
                int r  = wm * 32 + mf * 16 + (lane & 15);
                int cc = c0 + (lane >> 4);
                ldmx4(a[mf], sA + swz(r, cc));
            }
            uint32_t b[8][2];
            #pragma unroll
            for (int nb = 0; nb < 4; nb++) {
                int r  = wn * 64 + nb * 16 + (lane & 7) + ((lane >> 4) << 3);
                int cc = c0 + ((lane >> 3) & 1);
                uint32_t t4[4];
                ldmx4(t4, sW + swz(r, cc));
                b[2 * nb][0] = t4[0];     b[2 * nb][1] = t4[1];
                b[2 * nb + 1][0] = t4[2]; b[2 * nb + 1][1] = t4[3];
            }
            #pragma unroll
            for (int mf = 0; mf < 2; mf++)
                #pragma unroll
                for (int nf = 0; nf < 8; nf++)
                    mma16816(acc[mf][nf], a[mf], b[nf][0], b[nf][1]);
        }
    }

    // ---------------- epilogue ----------------
    float2 bn[8];
    #pragma unroll
    for (int nf = 0; nf < 8; nf++) {
        int col = nbase + wn * 64 + nf * 8 + (lane & 3) * 2;
        bn[nf].x = bias[col];
        bn[nf].y = bias[col + 1];
    }

    #pragma unroll
    for (int mf = 0; mf < 2; mf++) {
        #pragma unroll
        for (int half = 0; half < 2; half++) {
            const int row = mbase + wm * 32 + mf * 16 + (lane >> 2) + half * 8;
            const int colb = nbase + wn * 64 + (lane & 3) * 2;
            #pragma unroll
            for (int nf = 0; nf < 8; nf++) {
                const int col = colb + nf * 8;
                float g0 = gelu_f(acc[mf][nf][half * 2 + 0] + bn[nf].x);
                float g1 = gelu_f(acc[mf][nf][half * 2 + 1] + bn[nf].y);
                if (MODE == 0) {
                    const size_t ob = (size_t)row * DD + col;
                    __half2 hv;
                    hv.x = __float2half(g0);
                    hv.y = __float2half(g1);
                    *reinterpret_cast<__half2*>(outh + ob) = hv;
                } else if (MODE == 1) {
                    const size_t ob = (size_t)row * DD + col;
                    const int xr = row + a1_off;
                    float2 o;
                    if (xr >= 0) {
                        const size_t xb = (size_t)xr * DD + col;
                        __half2 xh2 = *reinterpret_cast<const __half2*>(a1 + xb);
                        o.x = g0 + __half2float(xh2.x);
                        o.y = g1 + __half2float(xh2.y);
                    } else { o.x = g0; o.y = g1; }
                    *reinterpret_cast<float2*>(outf + ob) = o;
                } else {
                    const size_t ob = (size_t)(row + out_off) * DD + col;
                    float2 o = *reinterpret_cast<float2*>(outf + ob);
                    o.x += g0; o.y += g1;
                    *reinterpret_cast<float2*>(outf + ob) = o;
                }
            }
        }
    }
}

// ---------------- cumsum over axis 0, in place ----------------
__global__ void cumsum_k(float* __restrict__ out) {
    int c = blockIdx.x * blockDim.x + threadIdx.x;
    float run = 0.f;
    #pragma unroll 4
    for (int s = 0; s < SS; s++) {
        size_t idx = (size_t)s * (BB * DD) + c;
        run += out[idx];
        out[idx] = run;
    }
}

extern "C" void kernel_launch(void* const* d_in, const int* in_sizes, int n_in,
                              void* d_out, int out_size)
{
    const float* src = nullptr; const float* map_w = nullptr; const float* bl_w = nullptr;
    const float* map_b = nullptr; const float* bl_b = nullptr;
    for (int i = 0; i < n_in; i++) {
        if (in_sizes[i] == NROWS * DD)       src   = (const float*)d_in[i];
        else if (in_sizes[i] == DD * DD)     map_w = (const float*)d_in[i];
        else if (in_sizes[i] == DD * 2 * DD) bl_w  = (const float*)d_in[i];
        else if (in_sizes[i] == DD) { if (!map_b) map_b = (const float*)d_in[i]; else bl_b = (const float*)d_in[i]; }
    }
    float* out = (float*)d_out;

    __half *sf, *h, *t, *mw, *w;
    cudaGetSymbolAddress((void**)&sf, g_src);
    cudaGetSymbolAddress((void**)&h,  g_h);
    cudaGetSymbolAddress((void**)&t,  g_t);
    cudaGetSymbolAddress((void**)&mw, g_mw);
    cudaGetSymbolAddress((void**)&w,  g_w);

    cudaFuncSetAttribute(mma_gemm<256, 0>, cudaFuncAttributeMaxDynamicSharedMemorySize, SMEM_BYTES);
    cudaFuncSetAttribute(mma_gemm<512, 0>, cudaFuncAttributeMaxDynamicSharedMemorySize, SMEM_BYTES);
    cudaFuncSetAttribute(mma_gemm<512, 1>, cudaFuncAttributeMaxDynamicSharedMemorySize, SMEM_BYTES);
    cudaFuncSetAttribute(mma_gemm<512, 2>, cudaFuncAttributeMaxDynamicSharedMemorySize, SMEM_BYTES);

    conv_k<<<(NROWS * DD / 4 + 255) / 256, 256>>>(src, sf, NROWS * DD);
    conv_k<<<(DD * DD / 4 + 255) / 256, 256>>>(map_w, mw, DD * DD);
    conv_k<<<(DD * 2 * DD / 4 + 255) / 256, 256>>>(bl_w, w, DD * 2 * DD);

    dim3 blk(256);
    dim3 gAll(NROWS / 128, 2);   // 1024 x 2
    dim3 gJ(JROWS / 128, 2);     // 1020 x 2

    // 1) h = gelu(src @ map_w^T + map_b) -> fp16
    mma_gemm<256, 0><<<gAll, blk, SMEM_BYTES>>>(sf, 0, sf, 0, mw, map_b,
                                                nullptr, 0, h);
    // 2) delta = x + blacket(x, h), x = h shifted by one step (BB rows)
    mma_gemm<512, 1><<<gAll, blk, SMEM_BYTES>>>(h, -BB, h, 0, w, bl_b,
                                                out, 0, nullptr);
    // 3) J terms: t = blacket(u, v); out[2B:] += blacket(w, t)
    mma_gemm<512, 0><<<gJ, blk, SMEM_BYTES>>>(h, BB,     h, 2 * BB, w, bl_b,
                                              nullptr, 0, t);
    mma_gemm<512, 2><<<gJ, blk, SMEM_BYTES>>>(h, 0,      t, 0,      w, bl_b,
                                              out, 2 * BB, nullptr);
    mma_gemm<512, 0><<<gJ, blk, SMEM_BYTES>>>(h, 2 * BB, h, 0,      w, bl_b,
                                              nullptr, 0, t);
    mma_gemm<512, 2><<<gJ, blk, SMEM_BYTES>>>(h, BB,     t, 0,      w, bl_b,
                                              out, 2 * BB, nullptr);
    mma_gemm<512, 0><<<gJ, blk, SMEM_BYTES>>>(h, 0,      h, BB,     w, bl_b,
                                              nullptr, 0, t);
    mma_gemm<512, 2><<<gJ, blk, SMEM_BYTES>>>(h, 2 * BB, t, 0,      w, bl_b,
                                              out, 2 * BB, nullptr);
    // 4) cumsum along axis 0
    cumsum_k<<<(BB * DD) / 256, 256>>>(out);
}